// round 7
// baseline (speedup 1.0000x reference)
#include <cuda_runtime.h>
#include <math.h>
#include <stdint.h>

#define B_ 4
#define T_ 2048
#define C_ 1024
#define H_ 16
#define D_ 64
#define M_ (B_*T_)      // 8192 rows
#define F_ (4*C_)       // 4096 ffn hidden
#define C3_ 3072        // fused qkv width

// ---------------- scratch (device globals; no allocations allowed) ----------
__device__ __align__(256) float g_xn  [M_*C_];
__device__ __align__(256) float g_qkv [M_*C3_];
__device__ __align__(256) float g_att [M_*C_];
__device__ __align__(256) float g_x1  [M_*C_];
__device__ __align__(256) float g_xn2 [M_*C_];
__device__ __align__(256) float g_h   [M_*F_];
__device__ __align__(256) float g_pw  [C3_*C_];   // fused qkv weights [3072][1024] K-major
__device__ __align__(256) float g_wpt [C_*C_];    // w_proj^T
__device__ __align__(256) float g_w1t [F_*C_];    // w1^T
__device__ __align__(256) float g_w2t [C_*F_];    // w2^T

// ======================= helpers =======================
__device__ __forceinline__ uint32_t smem_u32(const void* p) {
    uint32_t a;
    asm("{ .reg .u64 t; cvta.to.shared.u64 t, %1; cvt.u32.u64 %0, t; }" : "=r"(a) : "l"(p));
    return a;
}
__device__ __forceinline__ float rtf32(float x) {
    uint32_t u;
    asm("cvt.rna.tf32.f32 %0, %1;" : "=r"(u) : "f"(x));
    return __uint_as_float(u);
}
__device__ __forceinline__ void cp16(uint32_t dst, const void* src) {
    asm volatile("cp.async.cg.shared.global [%0], [%1], 16;" :: "r"(dst), "l"(src));
}
__device__ __forceinline__ void mma_tf32_frag(float* c, const uint32_t* a, uint32_t b0, uint32_t b1) {
    asm volatile(
        "mma.sync.aligned.m16n8k8.row.col.f32.tf32.tf32.f32 "
        "{%0,%1,%2,%3}, {%4,%5,%6,%7}, {%8,%9}, {%0,%1,%2,%3};\n"
        : "+f"(c[0]), "+f"(c[1]), "+f"(c[2]), "+f"(c[3])
        : "r"(a[0]), "r"(a[1]), "r"(a[2]), "r"(a[3]), "r"(b0), "r"(b1));
}

// ======================= LayerNorm (rounds output to tf32) =======
__global__ void ln_kernel(const float* __restrict__ x, const float* __restrict__ g,
                          const float* __restrict__ b, float* __restrict__ out)
{
    const int row = blockIdx.x, tid = threadIdx.x;
    float4 xv = ((const float4*)(x + (size_t)row * C_))[tid];
    __shared__ float r1[8], r2[8];

    float s = xv.x + xv.y + xv.z + xv.w;
    #pragma unroll
    for (int o = 16; o > 0; o >>= 1) s += __shfl_xor_sync(0xffffffffu, s, o);
    if ((tid & 31) == 0) r1[tid >> 5] = s;
    __syncthreads();
    float mu = (r1[0]+r1[1]+r1[2]+r1[3]+r1[4]+r1[5]+r1[6]+r1[7]) * (1.0f / C_);

    float d0 = xv.x - mu, d1 = xv.y - mu, d2 = xv.z - mu, d3 = xv.w - mu;
    float sq = d0*d0 + d1*d1 + d2*d2 + d3*d3;
    #pragma unroll
    for (int o = 16; o > 0; o >>= 1) sq += __shfl_xor_sync(0xffffffffu, sq, o);
    if ((tid & 31) == 0) r2[tid >> 5] = sq;
    __syncthreads();
    float rstd = rsqrtf((r2[0]+r2[1]+r2[2]+r2[3]+r2[4]+r2[5]+r2[6]+r2[7]) * (1.0f / C_) + 1e-5f);

    float4 gv = ((const float4*)g)[tid];
    float4 bv = ((const float4*)b)[tid];
    float4 o4;
    o4.x = rtf32(d0 * rstd * gv.x + bv.x);
    o4.y = rtf32(d1 * rstd * gv.y + bv.y);
    o4.z = rtf32(d2 * rstd * gv.z + bv.z);
    o4.w = rtf32(d3 * rstd * gv.w + bv.w);
    ((float4*)(out + (size_t)row * C_))[tid] = o4;
}

// ========== batched transpose: in[b][R][Cc] -> out[(b*Cc + c)*R + r], tf32-rounded ==========
__global__ void transpose_k(const float* __restrict__ in, float* __restrict__ out, int R, int Cc)
{
    __shared__ float t[32][33];
    const int b = blockIdx.z;
    const float* ib = in + (size_t)b * R * Cc;
    float* ob = out + (size_t)b * Cc * R;
    const int c0 = blockIdx.x * 32, r0 = blockIdx.y * 32;
    const int tx = threadIdx.x, ty = threadIdx.y;
    #pragma unroll
    for (int j = 0; j < 32; j += 8)
        t[ty + j][tx] = ib[(size_t)(r0 + ty + j) * Cc + c0 + tx];
    __syncthreads();
    #pragma unroll
    for (int j = 0; j < 32; j += 8)
        ob[(size_t)(c0 + ty + j) * R + r0 + tx] = rtf32(t[tx][ty + j]);
}

// ======================= tf32 mma.sync GEMM (3-stage pipeline) ==============
// D[M,N] = A[M,K] @ Bt[N,K]^T ; CTA tile 128x256, 8 warps (2x4), warp tile 64x64
// EPI bits: 1=+bias, 2=relu, 4=+residual, 8=round output to tf32
#define BM 128
#define BN 256
#define BKG 32
#define STR 36
#define ABUF (BM*STR)
#define BUFW ((BM+BN)*STR)
#define NSTAGE 3
#define GSMEM (NSTAGE*BUFW*4)     // 165888 bytes

template<int EPI>
__global__ void __launch_bounds__(256, 1) gemm_mma(
    const float* __restrict__ A, const float* __restrict__ Bt,
    float* __restrict__ Dm, const float* __restrict__ bias,
    const float* __restrict__ res, int M, int N, int K)
{
    extern __shared__ __align__(16) float sm[];
    const uint32_t sbase = smem_u32(sm);
    const int tid = threadIdx.x;
    const int wid = tid >> 5, lane = tid & 31;
    const int wm = (wid >> 2) * 64, wn = (wid & 3) * 64;
    const int g = lane >> 2, t = lane & 3;

    uint32_t gofs[12], sofs[12];
    #pragma unroll
    for (int s = 0; s < 12; s++) {
        int sid = s * 256 + tid;
        if (s < 4) {
            int row = sid >> 3, seg = sid & 7;
            gofs[s] = (uint32_t)((blockIdx.y * BM + row) * K + seg * 4);
            sofs[s] = (uint32_t)((row * STR + seg * 4) * 4);
        } else {
            int row = (sid - 1024) >> 3, seg = sid & 7;
            gofs[s] = (uint32_t)((blockIdx.x * BN + row) * K + seg * 4);
            sofs[s] = (uint32_t)(((BM + row) * STR + seg * 4) * 4);
        }
    }

    float acc[4][8][4];
    #pragma unroll
    for (int i = 0; i < 4; i++)
        #pragma unroll
        for (int j = 0; j < 8; j++)
            #pragma unroll
            for (int q = 0; q < 4; q++) acc[i][j][q] = 0.f;

    const int NIT = K / BKG;

    // prologue: stages 0,1
    #pragma unroll
    for (int c = 0; c < 2; c++) {
        uint32_t db = sbase + c * (BUFW * 4);
        uint32_t ko = (uint32_t)(c * BKG);
        #pragma unroll
        for (int s = 0; s < 4; s++)  cp16(db + sofs[s], A  + gofs[s] + ko);
        #pragma unroll
        for (int s = 4; s < 12; s++) cp16(db + sofs[s], Bt + gofs[s] + ko);
        asm volatile("cp.async.commit_group;");
    }

    #pragma unroll 1
    for (int it = 0; it < NIT; it++) {
        // stage `it` must be resident; at most the next group may remain in flight
        if (it < NIT - 1) asm volatile("cp.async.wait_group 1;");
        else              asm volatile("cp.async.wait_group 0;");
        __syncthreads();   // single barrier per iter: also retires compute(it-1)

        if (it + 2 < NIT) {      // prefetch stage it+2 (slot (it-1)%3: compute done)
            uint32_t db = sbase + ((it + 2) % NSTAGE) * (BUFW * 4);
            uint32_t ko = (uint32_t)((it + 2) * BKG);
            #pragma unroll
            for (int s = 0; s < 4; s++)  cp16(db + sofs[s], A  + gofs[s] + ko);
            #pragma unroll
            for (int s = 4; s < 12; s++) cp16(db + sofs[s], Bt + gofs[s] + ko);
            asm volatile("cp.async.commit_group;");
        }

        const float* Ab = sm + (it % NSTAGE) * BUFW;
        const float* Bb = Ab + ABUF;
        #pragma unroll
        for (int ks = 0; ks < 4; ks++) {
            const int k0 = ks * 8 + t;
            uint32_t a[4][4];
            #pragma unroll
            for (int i = 0; i < 4; i++) {
                const float* ap = Ab + (wm + i * 16 + g) * STR + k0;
                a[i][0] = __float_as_uint(ap[0]);
                a[i][1] = __float_as_uint(ap[8 * STR]);
                a[i][2] = __float_as_uint(ap[4]);
                a[i][3] = __float_as_uint(ap[8 * STR + 4]);
            }
            #pragma unroll
            for (int j = 0; j < 8; j++) {
                const float* bp = Bb + (wn + j * 8 + g) * STR + k0;
                uint32_t b0 = __float_as_uint(bp[0]);
                uint32_t b1 = __float_as_uint(bp[4]);
                #pragma unroll
                for (int i = 0; i < 4; i++)
                    mma_tf32_frag(acc[i][j], a[i], b0, b1);
            }
        }
    }

    #pragma unroll
    for (int i = 0; i < 4; i++) {
        const int m0 = blockIdx.y * BM + wm + i * 16 + g;
        #pragma unroll
        for (int j = 0; j < 8; j++) {
            const int n0 = blockIdx.x * BN + wn + j * 8 + t * 2;
            float2 v0 = make_float2(acc[i][j][0], acc[i][j][1]);
            float2 v1 = make_float2(acc[i][j][2], acc[i][j][3]);
            if (EPI & 1) {
                float2 bb = *(const float2*)(bias + n0);
                v0.x += bb.x; v0.y += bb.y; v1.x += bb.x; v1.y += bb.y;
            }
            if (EPI & 2) {
                v0.x = fmaxf(v0.x, 0.f); v0.y = fmaxf(v0.y, 0.f);
                v1.x = fmaxf(v1.x, 0.f); v1.y = fmaxf(v1.y, 0.f);
            }
            if (EPI & 4) {
                float2 r0 = *(const float2*)(res + (size_t)m0 * N + n0);
                float2 r1 = *(const float2*)(res + (size_t)(m0 + 8) * N + n0);
                v0.x += r0.x; v0.y += r0.y; v1.x += r1.x; v1.y += r1.y;
            }
            if (EPI & 8) {
                v0.x = rtf32(v0.x); v0.y = rtf32(v0.y);
                v1.x = rtf32(v1.x); v1.y = rtf32(v1.y);
            }
            *(float2*)(Dm + (size_t)m0 * N + n0) = v0;
            *(float2*)(Dm + (size_t)(m0 + 8) * N + n0) = v1;
        }
    }
}

// =============== tensor-core causal flash attention (tf32 mma.sync) ==========
// q-tile 128 x kv-tile 64; 8 warps, each warp owns 16 q-rows x 64 cols.
#define ASTR 68
#define AQ_OFF 0
#define AK_OFF (128*ASTR)
#define AV_OFF (AK_OFF + 64*ASTR)
#define AP_OFF (AV_OFF + 64*ASTR)
#define ASMEM ((AP_OFF + 128*ASTR) * 4)

__global__ void __launch_bounds__(256, 1) attn_mma(
    const float* __restrict__ QKV, float* __restrict__ O)
{
    extern __shared__ __align__(16) float as_[];
    float* Qs = as_ + AQ_OFF;
    float* Ks = as_ + AK_OFF;
    float* Vt = as_ + AV_OFF;
    float* Ps = as_ + AP_OFF;

    const int bh = blockIdx.x, qt = blockIdx.y;
    const int b = bh >> 4, h = bh & 15;
    const float* Qb = QKV + (size_t)b * T_ * C3_ + h * 64;
    const float* Kb = Qb + 1024;
    const float* Vb = Qb + 2048;
    float* Ob = O + (size_t)b * T_ * C_ + h * 64;

    const int tid = threadIdx.x;
    const int wid = tid >> 5, lane = tid & 31;
    const int g = lane >> 2, t = lane & 3;
    const int row0 = wid * 16;

    #pragma unroll
    for (int i = 0; i < 8; i++) {
        int idx = i * 256 + tid;
        int row = idx >> 4, c4 = (idx & 15) << 2;
        float4 qv = *(const float4*)(Qb + (size_t)(qt * 128 + row) * C3_ + c4);
        *(float4*)&Qs[row * ASTR + c4] = qv;
    }

    float m0 = -INFINITY, m1 = -INFINITY, l0 = 0.f, l1 = 0.f;
    float o[8][4];
    #pragma unroll
    for (int nf = 0; nf < 8; nf++)
        #pragma unroll
        for (int c = 0; c < 4; c++) o[nf][c] = 0.f;

    const int rqA = qt * 128 + row0 + g;
    const int rqB = rqA + 8;
    const int ktmax = 2 * qt + 1;

    #pragma unroll 1
    for (int kt = 0; kt <= ktmax; kt++) {
        __syncthreads();
        #pragma unroll
        for (int i = 0; i < 4; i++) {
            int idx = i * 256 + tid;
            int row = idx >> 4, c4 = (idx & 15) << 2;
            float4 kv = *(const float4*)(Kb + (size_t)(kt * 64 + row) * C3_ + c4);
            *(float4*)&Ks[row * ASTR + c4] = kv;
            float4 vv = *(const float4*)(Vb + (size_t)(kt * 64 + row) * C3_ + c4);
            Vt[(c4 + 0) * ASTR + row] = vv.x;
            Vt[(c4 + 1) * ASTR + row] = vv.y;
            Vt[(c4 + 2) * ASTR + row] = vv.z;
            Vt[(c4 + 3) * ASTR + row] = vv.w;
        }
        __syncthreads();

        float s[8][4];
        #pragma unroll
        for (int nf = 0; nf < 8; nf++)
            #pragma unroll
            for (int c = 0; c < 4; c++) s[nf][c] = 0.f;
        #pragma unroll
        for (int ks = 0; ks < 8; ks++) {
            const int k0 = ks * 8 + t;
            uint32_t a[4];
            const float* ap = Qs + (row0 + g) * ASTR + k0;
            a[0] = __float_as_uint(ap[0]);
            a[1] = __float_as_uint(ap[8 * ASTR]);
            a[2] = __float_as_uint(ap[4]);
            a[3] = __float_as_uint(ap[8 * ASTR + 4]);
            #pragma unroll
            for (int nf = 0; nf < 8; nf++) {
                const float* bp = Ks + (nf * 8 + g) * ASTR + k0;
                mma_tf32_frag(s[nf], a, __float_as_uint(bp[0]), __float_as_uint(bp[4]));
            }
        }

        const float scale = 0.03125f;
        const int colbase = kt * 64 + t * 2;
        float mxA = -INFINITY, mxB = -INFINITY;
        #pragma unroll
        for (int nf = 0; nf < 8; nf++) {
            #pragma unroll
            for (int c = 0; c < 2; c++) {
                int col = colbase + nf * 8 + c;
                float vA = s[nf][c] * scale;     if (col > rqA) vA = -INFINITY;
                float vB = s[nf][2 + c] * scale; if (col > rqB) vB = -INFINITY;
                s[nf][c] = vA; s[nf][2 + c] = vB;
                mxA = fmaxf(mxA, vA); mxB = fmaxf(mxB, vB);
            }
        }
        mxA = fmaxf(mxA, __shfl_xor_sync(0xffffffffu, mxA, 1));
        mxA = fmaxf(mxA, __shfl_xor_sync(0xffffffffu, mxA, 2));
        mxB = fmaxf(mxB, __shfl_xor_sync(0xffffffffu, mxB, 1));
        mxB = fmaxf(mxB, __shfl_xor_sync(0xffffffffu, mxB, 2));

        float mnA = fmaxf(m0, mxA), mnB = fmaxf(m1, mxB);
        float fA = __expf(m0 - mnA), fB = __expf(m1 - mnB);
        m0 = mnA; m1 = mnB;
        float rsA = 0.f, rsB = 0.f;
        #pragma unroll
        for (int nf = 0; nf < 8; nf++) {
            #pragma unroll
            for (int c = 0; c < 2; c++) {
                float pA = __expf(s[nf][c] - mnA);
                float pB = __expf(s[nf][2 + c] - mnB);
                s[nf][c] = pA; s[nf][2 + c] = pB;
                rsA += pA; rsB += pB;
            }
            o[nf][0] *= fA; o[nf][1] *= fA;
            o[nf][2] *= fB; o[nf][3] *= fB;
        }
        rsA += __shfl_xor_sync(0xffffffffu, rsA, 1);
        rsA += __shfl_xor_sync(0xffffffffu, rsA, 2);
        rsB += __shfl_xor_sync(0xffffffffu, rsB, 1);
        rsB += __shfl_xor_sync(0xffffffffu, rsB, 2);
        l0 = l0 * fA + rsA;
        l1 = l1 * fB + rsB;

        #pragma unroll
        for (int nf = 0; nf < 8; nf++) {
            *(float2*)&Ps[(row0 + g) * ASTR + nf * 8 + t * 2] =
                make_float2(rtf32(s[nf][0]), rtf32(s[nf][1]));
            *(float2*)&Ps[(row0 + g + 8) * ASTR + nf * 8 + t * 2] =
                make_float2(rtf32(s[nf][2]), rtf32(s[nf][3]));
        }
        __syncwarp();

        #pragma unroll
        for (int ks = 0; ks < 8; ks++) {
            const int k0 = ks * 8 + t;
            uint32_t a[4];
            const float* ap = Ps + (row0 + g) * ASTR + k0;
            a[0] = __float_as_uint(ap[0]);
            a[1] = __float_as_uint(ap[8 * ASTR]);
            a[2] = __float_as_uint(ap[4]);
            a[3] = __float_as_uint(ap[8 * ASTR + 4]);
            #pragma unroll
            for (int nf = 0; nf < 8; nf++) {
                const float* bp = Vt + (nf * 8 + g) * ASTR + k0;
                mma_tf32_frag(o[nf], a, __float_as_uint(bp[0]), __float_as_uint(bp[4]));
            }
        }
    }

    const float i0 = 1.0f / l0, i1 = 1.0f / l1;
    #pragma unroll
    for (int nf = 0; nf < 8; nf++) {
        int col = nf * 8 + t * 2;
        *(float2*)(Ob + (size_t)(qt * 128 + row0 + g) * C_ + col) =
            make_float2(rtf32(o[nf][0] * i0), rtf32(o[nf][1] * i0));
        *(float2*)(Ob + (size_t)(qt * 128 + row0 + g + 8) * C_ + col) =
            make_float2(rtf32(o[nf][2] * i1), rtf32(o[nf][3] * i1));
    }
}

// ---------------------------------------------------------------------------
extern "C" void kernel_launch(void* const* d_in, const int* in_sizes, int n_in,
                              void* d_out, int out_size)
{
    const float* x      = (const float*)d_in[0];
    const float* wq     = (const float*)d_in[1];
    const float* wk     = (const float*)d_in[2];
    const float* wv     = (const float*)d_in[3];
    const float* w_proj = (const float*)d_in[4];
    const float* b_proj = (const float*)d_in[5];
    const float* w1     = (const float*)d_in[6];
    const float* b1     = (const float*)d_in[7];
    const float* w2     = (const float*)d_in[8];
    const float* b2     = (const float*)d_in[9];
    const float* g1     = (const float*)d_in[10];
    const float* be1    = (const float*)d_in[11];
    const float* g2     = (const float*)d_in[12];
    const float* be2    = (const float*)d_in[13];
    float* out = (float*)d_out;

    float *xn, *qkv, *att, *x1, *xn2, *hb, *pw, *wpt, *w1t, *w2t;
    cudaGetSymbolAddress((void**)&xn,  g_xn);
    cudaGetSymbolAddress((void**)&qkv, g_qkv);
    cudaGetSymbolAddress((void**)&att, g_att);
    cudaGetSymbolAddress((void**)&x1,  g_x1);
    cudaGetSymbolAddress((void**)&xn2, g_xn2);
    cudaGetSymbolAddress((void**)&hb,  g_h);
    cudaGetSymbolAddress((void**)&pw,  g_pw);
    cudaGetSymbolAddress((void**)&wpt, g_wpt);
    cudaGetSymbolAddress((void**)&w1t, g_w1t);
    cudaGetSymbolAddress((void**)&w2t, g_w2t);

    cudaFuncSetAttribute(gemm_mma<8>,  cudaFuncAttributeMaxDynamicSharedMemorySize, GSMEM);
    cudaFuncSetAttribute(gemm_mma<5>,  cudaFuncAttributeMaxDynamicSharedMemorySize, GSMEM);
    cudaFuncSetAttribute(gemm_mma<11>, cudaFuncAttributeMaxDynamicSharedMemorySize, GSMEM);
    cudaFuncSetAttribute(attn_mma,     cudaFuncAttributeMaxDynamicSharedMemorySize, ASMEM);

    dim3 tb(32, 8);
    transpose_k<<<dim3(2, 32, 16), tb>>>(wq, pw,               C_, D_);
    transpose_k<<<dim3(2, 32, 16), tb>>>(wk, pw + C_ * C_,     C_, D_);
    transpose_k<<<dim3(2, 32, 16), tb>>>(wv, pw + 2 * C_ * C_, C_, D_);
    transpose_k<<<dim3(32, 32, 1),  tb>>>(w_proj, wpt, C_, C_);
    transpose_k<<<dim3(128, 32, 1), tb>>>(w1, w1t, C_, F_);
    transpose_k<<<dim3(32, 128, 1), tb>>>(w2, w2t, F_, C_);

    ln_kernel<<<M_, 256>>>(x, g1, be1, xn);
    gemm_mma<8><<<dim3(C3_ / BN, M_ / BM), 256, GSMEM>>>(xn, pw, qkv, nullptr, nullptr, M_, C3_, C_);
    attn_mma<<<dim3(B_ * H_, T_ / 128), 256, ASMEM>>>(qkv, att);
    gemm_mma<5><<<dim3(C_ / BN, M_ / BM), 256, GSMEM>>>(att, wpt, x1, b_proj, x, M_, C_, C_);
    ln_kernel<<<M_, 256>>>(x1, g2, be2, xn2);
    gemm_mma<11><<<dim3(F_ / BN, M_ / BM), 256, GSMEM>>>(xn2, w1t, hb, b1, nullptr, M_, F_, C_);
    gemm_mma<5><<<dim3(C_ / BN, M_ / BM), 256, GSMEM>>>(hb, w2t, out, b2, x1, M_, C_, F_);
}

// round 8
// speedup vs baseline: 1.6194x; 1.6194x over previous
#include <cuda_runtime.h>
#include <cuda_fp16.h>
#include <math.h>
#include <stdint.h>

#define B_ 4
#define T_ 2048
#define C_ 1024
#define H_ 16
#define D_ 64
#define M_ (B_*T_)      // 8192 rows
#define F_ (4*C_)       // 4096 ffn hidden
#define C3_ 3072        // fused qkv width

// ---------------- scratch (device globals; no allocations allowed) ----------
__device__ __align__(256) __half g_xn_h [M_*C_];
__device__ __align__(256) __half g_qkv_h[M_*C3_];
__device__ __align__(256) __half g_att_h[M_*C_];
__device__ __align__(256) __half g_xn2_h[M_*C_];
__device__ __align__(256) __half g_hh   [M_*F_];
__device__ __align__(256) float  g_x1   [M_*C_];
__device__ __align__(256) __half g_pw_h [C3_*C_];   // fused qkv weights [3072][1024] K-major
__device__ __align__(256) __half g_wpt_h[C_*C_];    // w_proj^T
__device__ __align__(256) __half g_w1t_h[F_*C_];    // w1^T
__device__ __align__(256) __half g_w2t_h[C_*F_];    // w2^T

// ======================= helpers =======================
__device__ __forceinline__ void cp16(uint32_t dst, const void* src) {
    asm volatile("cp.async.cg.shared.global [%0], [%1], 16;" :: "r"(dst), "l"(src));
}
__device__ __forceinline__ uint32_t smem_u32(const void* p) {
    uint32_t a;
    asm("{ .reg .u64 t; cvta.to.shared.u64 t, %1; cvt.u32.u64 %0, t; }" : "=r"(a) : "l"(p));
    return a;
}
__device__ __forceinline__ void mma_f16(float* c, const uint32_t* a, uint32_t b0, uint32_t b1) {
    asm volatile(
        "mma.sync.aligned.m16n8k16.row.col.f32.f16.f16.f32 "
        "{%0,%1,%2,%3}, {%4,%5,%6,%7}, {%8,%9}, {%0,%1,%2,%3};\n"
        : "+f"(c[0]), "+f"(c[1]), "+f"(c[2]), "+f"(c[3])
        : "r"(a[0]), "r"(a[1]), "r"(a[2]), "r"(a[3]), "r"(b0), "r"(b1));
}
__device__ __forceinline__ uint32_t h2u(float x, float y) {
    __half2 h = __floats2half2_rn(x, y);
    return *(uint32_t*)&h;
}

// ======================= LayerNorm (fp16 output) =======================
__global__ void ln_kernel(const float* __restrict__ x, const float* __restrict__ g,
                          const float* __restrict__ b, __half* __restrict__ out)
{
    const int row = blockIdx.x, tid = threadIdx.x;
    float4 xv = ((const float4*)(x + (size_t)row * C_))[tid];
    __shared__ float r1[8], r2[8];

    float s = xv.x + xv.y + xv.z + xv.w;
    #pragma unroll
    for (int o = 16; o > 0; o >>= 1) s += __shfl_xor_sync(0xffffffffu, s, o);
    if ((tid & 31) == 0) r1[tid >> 5] = s;
    __syncthreads();
    float mu = (r1[0]+r1[1]+r1[2]+r1[3]+r1[4]+r1[5]+r1[6]+r1[7]) * (1.0f / C_);

    float d0 = xv.x - mu, d1 = xv.y - mu, d2 = xv.z - mu, d3 = xv.w - mu;
    float sq = d0*d0 + d1*d1 + d2*d2 + d3*d3;
    #pragma unroll
    for (int o = 16; o > 0; o >>= 1) sq += __shfl_xor_sync(0xffffffffu, sq, o);
    if ((tid & 31) == 0) r2[tid >> 5] = sq;
    __syncthreads();
    float rstd = rsqrtf((r2[0]+r2[1]+r2[2]+r2[3]+r2[4]+r2[5]+r2[6]+r2[7]) * (1.0f / C_) + 1e-5f);

    float4 gv = ((const float4*)g)[tid];
    float4 bv = ((const float4*)b)[tid];
    uint2 u;
    u.x = h2u(d0 * rstd * gv.x + bv.x, d1 * rstd * gv.y + bv.y);
    u.y = h2u(d2 * rstd * gv.z + bv.z, d3 * rstd * gv.w + bv.w);
    ((uint2*)(out + (size_t)row * C_))[tid] = u;
}

// ========== batched transpose: in[b][R][Cc] -> out[(b*Cc + c)*R + r], fp16 ==========
__global__ void transpose_k(const float* __restrict__ in, __half* __restrict__ out, int R, int Cc)
{
    __shared__ float t[32][33];
    const int b = blockIdx.z;
    const float* ib = in + (size_t)b * R * Cc;
    __half* ob = out + (size_t)b * Cc * R;
    const int c0 = blockIdx.x * 32, r0 = blockIdx.y * 32;
    const int tx = threadIdx.x, ty = threadIdx.y;
    #pragma unroll
    for (int j = 0; j < 32; j += 8)
        t[ty + j][tx] = ib[(size_t)(r0 + ty + j) * Cc + c0 + tx];
    __syncthreads();
    #pragma unroll
    for (int j = 0; j < 32; j += 8)
        ob[(size_t)(c0 + ty + j) * R + r0 + tx] = __float2half_rn(t[tx][ty + j]);
}

// ======================= fp16 mma.sync GEMM (3-stage pipeline) ==============
// D[M,N] = A[M,K] @ Bt[N,K]^T, fp16 in / f32 accumulate
// CTA tile 128x256, 8 warps (2x4), warp tile 64x64, BK=32 halves
// EPI bits: 1=+bias, 2=relu, 4=+residual(f32), 8=write f32 D, 16=write half Dh
#define BM 128
#define BN 256
#define BKG 32
#define SH 40                       // halves per smem row (word-stride 20: conflict-free)
#define ABUF (BM*SH)                // halves
#define BUFW ((BM+BN)*SH)           // 15360 halves per stage
#define NSTAGE 3
#define GSMEM (NSTAGE*BUFW*2)       // 92160 bytes

template<int EPI>
__global__ void __launch_bounds__(256, 1) gemm_mma(
    const __half* __restrict__ A, const __half* __restrict__ Bt,
    float* __restrict__ Dm, __half* __restrict__ Dh,
    const float* __restrict__ bias, const float* __restrict__ res,
    int M, int N, int K)
{
    extern __shared__ __align__(16) __half smh[];
    const uint32_t sbase = smem_u32(smh);
    const int tid = threadIdx.x;
    const int wid = tid >> 5, lane = tid & 31;
    const int wm = (wid >> 2) * 64, wn = (wid & 3) * 64;
    const int g = lane >> 2, t = lane & 3;

    // 6 cp.async 16B chunks per thread: s=0,1 -> A tile (512), s=2..5 -> B (1024)
    uint32_t gofs[6], sofs[6];
    #pragma unroll
    for (int s = 0; s < 6; s++) {
        int sid = s * 256 + tid;
        if (sid < 512) {
            int row = sid >> 2, seg = sid & 3;
            gofs[s] = (uint32_t)((blockIdx.y * BM + row) * K + seg * 8);
            sofs[s] = (uint32_t)((row * SH + seg * 8) * 2);
        } else {
            sid -= 512;
            int row = sid >> 2, seg = sid & 3;
            gofs[s] = (uint32_t)((blockIdx.x * BN + row) * K + seg * 8);
            sofs[s] = (uint32_t)(((BM + row) * SH + seg * 8) * 2);
        }
    }

    float acc[4][8][4];
    #pragma unroll
    for (int i = 0; i < 4; i++)
        #pragma unroll
        for (int j = 0; j < 8; j++)
            #pragma unroll
            for (int q = 0; q < 4; q++) acc[i][j][q] = 0.f;

    const int NIT = K / BKG;

    #pragma unroll
    for (int c = 0; c < 2; c++) {
        uint32_t db = sbase + c * (BUFW * 2);
        uint32_t ko = (uint32_t)(c * BKG);
        #pragma unroll
        for (int s = 0; s < 2; s++) cp16(db + sofs[s], A  + gofs[s] + ko);
        #pragma unroll
        for (int s = 2; s < 6; s++) cp16(db + sofs[s], Bt + gofs[s] + ko);
        asm volatile("cp.async.commit_group;");
    }

    #pragma unroll 1
    for (int it = 0; it < NIT; it++) {
        if (it < NIT - 1) asm volatile("cp.async.wait_group 1;");
        else              asm volatile("cp.async.wait_group 0;");
        __syncthreads();

        if (it + 2 < NIT) {
            uint32_t db = sbase + ((it + 2) % NSTAGE) * (BUFW * 2);
            uint32_t ko = (uint32_t)((it + 2) * BKG);
            #pragma unroll
            for (int s = 0; s < 2; s++) cp16(db + sofs[s], A  + gofs[s] + ko);
            #pragma unroll
            for (int s = 2; s < 6; s++) cp16(db + sofs[s], Bt + gofs[s] + ko);
            asm volatile("cp.async.commit_group;");
        }

        const __half* Ab = smh + (it % NSTAGE) * BUFW;
        const __half* Bb = Ab + ABUF;
        #pragma unroll
        for (int ks = 0; ks < 2; ks++) {
            const int k0 = ks * 16 + 2 * t;
            uint32_t a[4][4];
            #pragma unroll
            for (int i = 0; i < 4; i++) {
                const __half* ap = Ab + (wm + i * 16 + g) * SH + k0;
                a[i][0] = *(const uint32_t*)(ap);
                a[i][1] = *(const uint32_t*)(ap + 8 * SH);
                a[i][2] = *(const uint32_t*)(ap + 8);
                a[i][3] = *(const uint32_t*)(ap + 8 * SH + 8);
            }
            #pragma unroll
            for (int j = 0; j < 8; j++) {
                const __half* bp = Bb + (wn + j * 8 + g) * SH + k0;
                uint32_t b0 = *(const uint32_t*)(bp);
                uint32_t b1 = *(const uint32_t*)(bp + 8);
                #pragma unroll
                for (int i = 0; i < 4; i++)
                    mma_f16(acc[i][j], a[i], b0, b1);
            }
        }
    }

    #pragma unroll
    for (int i = 0; i < 4; i++) {
        const int m0 = blockIdx.y * BM + wm + i * 16 + g;
        #pragma unroll
        for (int j = 0; j < 8; j++) {
            const int n0 = blockIdx.x * BN + wn + j * 8 + t * 2;
            float2 v0 = make_float2(acc[i][j][0], acc[i][j][1]);
            float2 v1 = make_float2(acc[i][j][2], acc[i][j][3]);
            if (EPI & 1) {
                float2 bb = *(const float2*)(bias + n0);
                v0.x += bb.x; v0.y += bb.y; v1.x += bb.x; v1.y += bb.y;
            }
            if (EPI & 2) {
                v0.x = fmaxf(v0.x, 0.f); v0.y = fmaxf(v0.y, 0.f);
                v1.x = fmaxf(v1.x, 0.f); v1.y = fmaxf(v1.y, 0.f);
            }
            if (EPI & 4) {
                float2 r0 = *(const float2*)(res + (size_t)m0 * N + n0);
                float2 r1 = *(const float2*)(res + (size_t)(m0 + 8) * N + n0);
                v0.x += r0.x; v0.y += r0.y; v1.x += r1.x; v1.y += r1.y;
            }
            if (EPI & 8) {
                *(float2*)(Dm + (size_t)m0 * N + n0) = v0;
                *(float2*)(Dm + (size_t)(m0 + 8) * N + n0) = v1;
            }
            if (EPI & 16) {
                *(uint32_t*)(Dh + (size_t)m0 * N + n0) = h2u(v0.x, v0.y);
                *(uint32_t*)(Dh + (size_t)(m0 + 8) * N + n0) = h2u(v1.x, v1.y);
            }
        }
    }
}

// =============== fp16 tensor-core causal flash attention =====================
// q-tile 128 x kv-tile 64; 8 warps, each warp 16 q-rows x 64 cols.
// P passes from S-mma accumulator to PV-mma A-fragment entirely in registers.
#define ASH 72                          // halves per smem row (word-stride 36)
#define AQ_OFF 0                        // Qs 128 x ASH
#define AK_OFF (128*ASH)                // Ks 64 x ASH
#define AV_OFF (AK_OFF + 64*ASH)        // Vt 64 x ASH (Vt[d][s])
#define ASMEM ((AV_OFF + 64*ASH) * 2)   // 36864 bytes

__global__ void __launch_bounds__(256, 1) attn_mma(
    const __half* __restrict__ QKV, __half* __restrict__ O)
{
    extern __shared__ __align__(16) __half ah_[];
    __half* Qs = ah_ + AQ_OFF;
    __half* Ks = ah_ + AK_OFF;
    __half* Vt = ah_ + AV_OFF;

    const int bh = blockIdx.x, qt = blockIdx.y;
    const int b = bh >> 4, h = bh & 15;
    const __half* Qb = QKV + (size_t)b * T_ * C3_ + h * 64;
    const __half* Kb = Qb + 1024;
    const __half* Vb = Qb + 2048;
    __half* Ob = O + (size_t)b * T_ * C_ + h * 64;

    const int tid = threadIdx.x;
    const int wid = tid >> 5, lane = tid & 31;
    const int g = lane >> 2, t = lane & 3;
    const int row0 = wid * 16;

    // load Q tile: 128 rows x 64 halves
    #pragma unroll
    for (int i = 0; i < 4; i++) {
        int idx = i * 256 + tid;
        int row = idx >> 3, seg = idx & 7;
        uint4 v = *(const uint4*)(Qb + (size_t)(qt * 128 + row) * C3_ + seg * 8);
        uint2* d = (uint2*)&Qs[row * ASH + seg * 8];
        d[0] = make_uint2(v.x, v.y);
        d[1] = make_uint2(v.z, v.w);
    }

    float m0 = -INFINITY, m1 = -INFINITY, l0 = 0.f, l1 = 0.f;
    float o[8][4];
    #pragma unroll
    for (int nf = 0; nf < 8; nf++)
        #pragma unroll
        for (int c = 0; c < 4; c++) o[nf][c] = 0.f;

    const int rqA = qt * 128 + row0 + g;
    const int rqB = rqA + 8;
    const int ktmax = 2 * qt + 1;

    #pragma unroll 1
    for (int kt = 0; kt <= ktmax; kt++) {
        __syncthreads();   // prior iter done reading Ks/Vt (and Q stores on iter 0)
        #pragma unroll
        for (int i = 0; i < 2; i++) {
            int idx = i * 256 + tid;
            int row = idx >> 3, seg = idx & 7;
            uint4 kv = *(const uint4*)(Kb + (size_t)(kt * 64 + row) * C3_ + seg * 8);
            uint2* d = (uint2*)&Ks[row * ASH + seg * 8];
            d[0] = make_uint2(kv.x, kv.y);
            d[1] = make_uint2(kv.z, kv.w);
            uint4 vv = *(const uint4*)(Vb + (size_t)(kt * 64 + row) * C3_ + seg * 8);
            const __half* hp = (const __half*)&vv;
            #pragma unroll
            for (int mq = 0; mq < 8; mq++)
                Vt[(seg * 8 + mq) * ASH + row] = hp[mq];
        }
        __syncthreads();

        // S = Q K^T  (16 x 64 per warp, d = 64 -> 4 k16 steps)
        float s[8][4];
        #pragma unroll
        for (int nf = 0; nf < 8; nf++)
            #pragma unroll
            for (int c = 0; c < 4; c++) s[nf][c] = 0.f;
        #pragma unroll
        for (int ks = 0; ks < 4; ks++) {
            const int k0 = ks * 16 + 2 * t;
            uint32_t a[4];
            const __half* ap = Qs + (row0 + g) * ASH + k0;
            a[0] = *(const uint32_t*)(ap);
            a[1] = *(const uint32_t*)(ap + 8 * ASH);
            a[2] = *(const uint32_t*)(ap + 8);
            a[3] = *(const uint32_t*)(ap + 8 * ASH + 8);
            #pragma unroll
            for (int nf = 0; nf < 8; nf++) {
                const __half* bp = Ks + (nf * 8 + g) * ASH + k0;
                mma_f16(s[nf], a, *(const uint32_t*)bp, *(const uint32_t*)(bp + 8));
            }
        }

        // scale + causal mask + online softmax
        const float scale = 0.03125f;
        const int colbase = kt * 64 + 2 * t;
        float mxA = -INFINITY, mxB = -INFINITY;
        #pragma unroll
        for (int nf = 0; nf < 8; nf++) {
            #pragma unroll
            for (int c = 0; c < 2; c++) {
                int col = colbase + nf * 8 + c;
                float vA = s[nf][c] * scale;     if (col > rqA) vA = -INFINITY;
                float vB = s[nf][2 + c] * scale; if (col > rqB) vB = -INFINITY;
                s[nf][c] = vA; s[nf][2 + c] = vB;
                mxA = fmaxf(mxA, vA); mxB = fmaxf(mxB, vB);
            }
        }
        mxA = fmaxf(mxA, __shfl_xor_sync(0xffffffffu, mxA, 1));
        mxA = fmaxf(mxA, __shfl_xor_sync(0xffffffffu, mxA, 2));
        mxB = fmaxf(mxB, __shfl_xor_sync(0xffffffffu, mxB, 1));
        mxB = fmaxf(mxB, __shfl_xor_sync(0xffffffffu, mxB, 2));

        float mnA = fmaxf(m0, mxA), mnB = fmaxf(m1, mxB);
        float fA = __expf(m0 - mnA), fB = __expf(m1 - mnB);
        m0 = mnA; m1 = mnB;
        float rsA = 0.f, rsB = 0.f;
        #pragma unroll
        for (int nf = 0; nf < 8; nf++) {
            #pragma unroll
            for (int c = 0; c < 2; c++) {
                float pA = __expf(s[nf][c] - mnA);
                float pB = __expf(s[nf][2 + c] - mnB);
                s[nf][c] = pA; s[nf][2 + c] = pB;
                rsA += pA; rsB += pB;
            }
            o[nf][0] *= fA; o[nf][1] *= fA;
            o[nf][2] *= fB; o[nf][3] *= fB;
        }
        rsA += __shfl_xor_sync(0xffffffffu, rsA, 1);
        rsA += __shfl_xor_sync(0xffffffffu, rsA, 2);
        rsB += __shfl_xor_sync(0xffffffffu, rsB, 1);
        rsB += __shfl_xor_sync(0xffffffffu, rsB, 2);
        l0 = l0 * fA + rsA;
        l1 = l1 * fB + rsB;

        // O += P @ V — P goes straight from S accumulator regs to A fragments
        #pragma unroll
        for (int ks = 0; ks < 4; ks++) {
            uint32_t a[4];
            a[0] = h2u(s[2 * ks][0],     s[2 * ks][1]);
            a[1] = h2u(s[2 * ks][2],     s[2 * ks][3]);
            a[2] = h2u(s[2 * ks + 1][0], s[2 * ks + 1][1]);
            a[3] = h2u(s[2 * ks + 1][2], s[2 * ks + 1][3]);
            const int k0 = ks * 16 + 2 * t;
            #pragma unroll
            for (int nf = 0; nf < 8; nf++) {
                const __half* bp = Vt + (nf * 8 + g) * ASH + k0;
                mma_f16(o[nf], a, *(const uint32_t*)bp, *(const uint32_t*)(bp + 8));
            }
        }
    }

    const float i0 = 1.0f / l0, i1 = 1.0f / l1;
    #pragma unroll
    for (int nf = 0; nf < 8; nf++) {
        int col = nf * 8 + 2 * t;
        *(uint32_t*)(Ob + (size_t)(qt * 128 + row0 + g) * C_ + col) =
            h2u(o[nf][0] * i0, o[nf][1] * i0);
        *(uint32_t*)(Ob + (size_t)(qt * 128 + row0 + g + 8) * C_ + col) =
            h2u(o[nf][2] * i1, o[nf][3] * i1);
    }
}

// ---------------------------------------------------------------------------
extern "C" void kernel_launch(void* const* d_in, const int* in_sizes, int n_in,
                              void* d_out, int out_size)
{
    const float* x      = (const float*)d_in[0];
    const float* wq     = (const float*)d_in[1];
    const float* wk     = (const float*)d_in[2];
    const float* wv     = (const float*)d_in[3];
    const float* w_proj = (const float*)d_in[4];
    const float* b_proj = (const float*)d_in[5];
    const float* w1     = (const float*)d_in[6];
    const float* b1     = (const float*)d_in[7];
    const float* w2     = (const float*)d_in[8];
    const float* b2     = (const float*)d_in[9];
    const float* g1     = (const float*)d_in[10];
    const float* be1    = (const float*)d_in[11];
    const float* g2     = (const float*)d_in[12];
    const float* be2    = (const float*)d_in[13];
    float* out = (float*)d_out;

    __half *xn, *qkv, *att, *xn2, *hb, *pw, *wpt, *w1t, *w2t;
    float *x1;
    cudaGetSymbolAddress((void**)&xn,  g_xn_h);
    cudaGetSymbolAddress((void**)&qkv, g_qkv_h);
    cudaGetSymbolAddress((void**)&att, g_att_h);
    cudaGetSymbolAddress((void**)&xn2, g_xn2_h);
    cudaGetSymbolAddress((void**)&hb,  g_hh);
    cudaGetSymbolAddress((void**)&x1,  g_x1);
    cudaGetSymbolAddress((void**)&pw,  g_pw_h);
    cudaGetSymbolAddress((void**)&wpt, g_wpt_h);
    cudaGetSymbolAddress((void**)&w1t, g_w1t_h);
    cudaGetSymbolAddress((void**)&w2t, g_w2t_h);

    cudaFuncSetAttribute(gemm_mma<16>, cudaFuncAttributeMaxDynamicSharedMemorySize, GSMEM);
    cudaFuncSetAttribute(gemm_mma<13>, cudaFuncAttributeMaxDynamicSharedMemorySize, GSMEM);
    cudaFuncSetAttribute(gemm_mma<19>, cudaFuncAttributeMaxDynamicSharedMemorySize, GSMEM);
    cudaFuncSetAttribute(attn_mma,     cudaFuncAttributeMaxDynamicSharedMemorySize, ASMEM);

    dim3 tb(32, 8);
    transpose_k<<<dim3(2, 32, 16), tb>>>(wq, pw,               C_, D_);
    transpose_k<<<dim3(2, 32, 16), tb>>>(wk, pw + C_ * C_,     C_, D_);
    transpose_k<<<dim3(2, 32, 16), tb>>>(wv, pw + 2 * C_ * C_, C_, D_);
    transpose_k<<<dim3(32, 32, 1),  tb>>>(w_proj, wpt, C_, C_);
    transpose_k<<<dim3(128, 32, 1), tb>>>(w1, w1t, C_, F_);
    transpose_k<<<dim3(32, 128, 1), tb>>>(w2, w2t, F_, C_);

    // LN1 (fp16 out)
    ln_kernel<<<M_, 256>>>(x, g1, be1, xn);
    // fused QKV projection -> fp16 qkv
    gemm_mma<16><<<dim3(C3_ / BN, M_ / BM), 256, GSMEM>>>(xn, pw, nullptr, qkv, nullptr, nullptr, M_, C3_, C_);
    // causal attention on fp16 tensor cores -> fp16 att
    attn_mma<<<dim3(B_ * H_, T_ / 128), 256, ASMEM>>>(qkv, att);
    // out projection + bias + residual(x) -> f32 x1
    gemm_mma<13><<<dim3(C_ / BN, M_ / BM), 256, GSMEM>>>(att, wpt, x1, nullptr, b_proj, x, M_, C_, C_);
    // LN2 (fp16 out)
    ln_kernel<<<M_, 256>>>(x1, g2, be2, xn2);
    // FFN1: bias + relu -> fp16 h
    gemm_mma<19><<<dim3(F_ / BN, M_ / BM), 256, GSMEM>>>(xn2, w1t, nullptr, hb, b1, nullptr, M_, F_, C_);
    // FFN2: bias + residual(x1) -> f32 out
    gemm_mma<13><<<dim3(C_ / BN, M_ / BM), 256, GSMEM>>>(hb, w2t, out, nullptr, b2, x1, M_, C_, F_);
}